// round 14
// baseline (speedup 1.0000x reference)
#include <cuda_runtime.h>
#include <cuda_bf16.h>
#include <math_constants.h>

// Problem constants (fixed by setup_inputs)
#define B_   4
#define N_   8192
#define BN_  (B_ * N_)      // 32768 points
#define DIN  64
#define DPRE 67             // feature(64) + xyz(3)
#define C_   128            // D_OUT
#define K_   36

// spatial grid
#define G_   16
#define GC_  (G_ * G_ * G_)   // 4096 cells per batch

// fused kernel partition
#define KNN_BLOCKS  4096
#define PREP_BLOCKS 128
#define FUSED_SMEM  (8 * 4 * 68 * 4)   // per-warp point staging only (8.7KB)

// ---------------- device scratch (no allocations allowed) ----------------
__device__ float  g_EP [BN_ * C_];   // exp(Wr_left @ pre)           (sorted order)
__device__ float  g_EQ [BN_ * C_];   // exp((Wr_r - Wr_l) @ pre + br)(sorted order)
__device__ float  g_V  [BN_ * C_];   // relu(Wv @ pre + bv)          (sorted order)
__device__ float  g_mid[BN_ * C_];   // attention output             (sorted order)
__device__ int    g_nbr[BN_ * K_];   // knn neighbor SORTED positions
__device__ int    g_cellcnt [B_ * GC_];
__device__ int    g_cellstart[B_ * GC_];
__device__ int    g_cellid[BN_];     // per original point: within-batch cell
__device__ int    g_rank  [BN_];     // atomic rank within cell (pre-sort)
__device__ float4 g_pts4 [BN_];      // sorted points (x,y,z,pad)
__device__ int    g_pid  [BN_];      // sorted pos -> original global id
__device__ int    g_spos [BN_];      // original global id -> sorted pos
__device__ float  g_WA[DPRE * C_];   // Wr_left   transposed [d][c]
__device__ float  g_WB[DPRE * C_];   // Wr_right - Wr_left   [d][c]
__device__ float  g_WC[DPRE * C_];   // Wv                   [d][c]

// ---------------- fast exp (FMA pipe) ------------------------------------
__device__ __forceinline__ float fast_exp(float x) {
    float y = x * 1.4426950408889634f;      // x * log2(e)
    int   e = __float2int_rn(y);
    float f = y - (float)e;                 // f in [-0.5, 0.5]
    float p =            1.5403530393381609e-4f;
    p = fmaf(p, f, 1.3333558146428443e-3f);
    p = fmaf(p, f, 9.6181291076284770e-3f);
    p = fmaf(p, f, 5.5504108664821580e-2f);
    p = fmaf(p, f, 2.4022650695910070e-1f);
    p = fmaf(p, f, 6.9314718055994530e-1f);
    p = fmaf(p, f, 1.0f);
    float s = __int_as_float((e + 127) << 23);
    return p * s;
}

// ============================================================================
// Weight transpose: [c][d] -> [d][c] global arrays (same values and the same
// WrR - WrL subtraction as the old smem staging => bit-identical prep math).
// ============================================================================
__global__ void wxpose_kernel(const float* __restrict__ Wr,
                              const float* __restrict__ Wv) {
    int i = blockIdx.x * blockDim.x + threadIdx.x;
    if (i >= DPRE * C_) return;
    int d = i >> 7, c = i & 127;
    float a = Wr[c * 134 + d];
    g_WA[i] = a;
    g_WB[i] = Wr[c * 134 + DPRE + d] - a;
    g_WC[i] = Wv[c * DPRE + d];
}

// ============================================================================
// Grid build (R5 pipeline — proven fastest config)
// ============================================================================
__global__ void cellassign_kernel(const float* __restrict__ xyz) {
    int m = blockIdx.x * blockDim.x + threadIdx.x;
    if (m >= BN_) return;
    int b = m >> 13;
    float x = xyz[(size_t)m * 3 + 0];
    float y = xyz[(size_t)m * 3 + 1];
    float z = xyz[(size_t)m * 3 + 2];
    int cx = min(G_ - 1, max(0, (int)(x * (float)G_)));
    int cy = min(G_ - 1, max(0, (int)(y * (float)G_)));
    int cz = min(G_ - 1, max(0, (int)(z * (float)G_)));
    int cell = (cx * G_ + cy) * G_ + cz;
    int r = atomicAdd(&g_cellcnt[b * GC_ + cell], 1);
    g_cellid[m] = cell;
    g_rank[m] = r;
}

__global__ void scan_kernel() {
    __shared__ int s[1024];
    int b = blockIdx.x;
    int t = threadIdx.x;
    int c0 = g_cellcnt[b * GC_ + 4 * t + 0];
    int c1 = g_cellcnt[b * GC_ + 4 * t + 1];
    int c2 = g_cellcnt[b * GC_ + 4 * t + 2];
    int c3 = g_cellcnt[b * GC_ + 4 * t + 3];
    int tot = c0 + c1 + c2 + c3;
    s[t] = tot;
    __syncthreads();
    for (int off = 1; off < 1024; off <<= 1) {
        int x = (t >= off) ? s[t - off] : 0;
        __syncthreads();
        s[t] += x;
        __syncthreads();
    }
    int excl = s[t] - tot;
    g_cellstart[b * GC_ + 4 * t + 0] = excl;
    g_cellstart[b * GC_ + 4 * t + 1] = excl + c0;
    g_cellstart[b * GC_ + 4 * t + 2] = excl + c0 + c1;
    g_cellstart[b * GC_ + 4 * t + 3] = excl + c0 + c1 + c2;
}

__global__ void scatter_kernel(const float* __restrict__ xyz) {
    int m = blockIdx.x * blockDim.x + threadIdx.x;
    if (m >= BN_) return;
    int b = m >> 13;
    int cell = g_cellid[m];
    int p = b * N_ + g_cellstart[b * GC_ + cell] + g_rank[m];
    float x = xyz[(size_t)m * 3 + 0];
    float y = xyz[(size_t)m * 3 + 1];
    float z = xyz[(size_t)m * 3 + 2];
    g_pts4[p] = make_float4(x, y, z, 0.0f);
    g_pid[p] = m;
}

__global__ void sortfix_kernel() {
    int i = blockIdx.x * blockDim.x + threadIdx.x;
    if (i >= B_ * GC_) return;
    int b = i / GC_;
    int cell = i - b * GC_;
    int start = b * N_ + g_cellstart[b * GC_ + cell];
    int cnt = g_cellcnt[b * GC_ + cell];
    for (int a = 1; a < cnt; a++) {
        int pid = g_pid[start + a];
        float4 pt = g_pts4[start + a];
        int j = a - 1;
        while (j >= 0 && g_pid[start + j] > pid) {
            g_pid[start + j + 1]  = g_pid[start + j];
            g_pts4[start + j + 1] = g_pts4[start + j];
            j--;
        }
        g_pid[start + j + 1]  = pid;
        g_pts4[start + j + 1] = pt;
    }
    for (int a = 0; a < cnt; a++) g_spos[g_pid[start + a]] = start + a;
}

// ============================================================================
// prep body (device fn): per-point EP/EQ/V, written in SORTED order.
// Weights from pre-transposed global arrays (coalesced float4 LDG, L1-hot).
// 256-thread blocks, 8 warps, 32 points/warp. Bit-identical math to R13.
// ============================================================================
__device__ __forceinline__ void prep_body(int pb,
                                          const float* __restrict__ feat,
                                          const float* __restrict__ xyz,
                                          const float* __restrict__ br,
                                          const float* __restrict__ bv,
                                          float* sPre) {
    int t = threadIdx.x;
    int w = t >> 5, lane = t & 31;
    float4 br4 = *(const float4*)&br[4 * lane];
    float4 bv4 = *(const float4*)&bv[4 * lane];
    float* spw = sPre + w * 4 * 68;

    int base = pb * 256 + w * 32;           // 32 points per warp
    for (int it = 0; it < 8; it++) {
        int m0 = base + it * 4;
        #pragma unroll
        for (int p = 0; p < 4; p++) {
            int m = m0 + p;
            spw[p * 68 + lane]      = feat[(size_t)m * 64 + lane];
            spw[p * 68 + 32 + lane] = feat[(size_t)m * 64 + 32 + lane];
            if (lane < 3) spw[p * 68 + 64 + lane] = xyz[(size_t)m * 3 + lane];
        }
        __syncwarp();

        float aP[4][4], aQ[4][4], aV[4][4];
        #pragma unroll
        for (int p = 0; p < 4; p++)
            #pragma unroll
            for (int r = 0; r < 4; r++) { aP[p][r] = 0.f; aQ[p][r] = 0.f; aV[p][r] = 0.f; }

        for (int d = 0; d < DPRE; d++) {
            float4 wa = *(const float4*)&g_WA[d * C_ + 4 * lane];
            float4 wb = *(const float4*)&g_WB[d * C_ + 4 * lane];
            float4 wc = *(const float4*)&g_WC[d * C_ + 4 * lane];
            #pragma unroll
            for (int p = 0; p < 4; p++) {
                float x = spw[p * 68 + d];
                aP[p][0] = fmaf(wa.x, x, aP[p][0]);
                aP[p][1] = fmaf(wa.y, x, aP[p][1]);
                aP[p][2] = fmaf(wa.z, x, aP[p][2]);
                aP[p][3] = fmaf(wa.w, x, aP[p][3]);
                aQ[p][0] = fmaf(wb.x, x, aQ[p][0]);
                aQ[p][1] = fmaf(wb.y, x, aQ[p][1]);
                aQ[p][2] = fmaf(wb.z, x, aQ[p][2]);
                aQ[p][3] = fmaf(wb.w, x, aQ[p][3]);
                aV[p][0] = fmaf(wc.x, x, aV[p][0]);
                aV[p][1] = fmaf(wc.y, x, aV[p][1]);
                aV[p][2] = fmaf(wc.z, x, aV[p][2]);
                aV[p][3] = fmaf(wc.w, x, aV[p][3]);
            }
        }
        #pragma unroll
        for (int p = 0; p < 4; p++) {
            size_t sp = (size_t)g_spos[m0 + p];     // sorted destination
            float4 ep, eq, vv;
            ep.x = fast_exp(aP[p][0]); ep.y = fast_exp(aP[p][1]);
            ep.z = fast_exp(aP[p][2]); ep.w = fast_exp(aP[p][3]);
            eq.x = fast_exp(aQ[p][0] + br4.x); eq.y = fast_exp(aQ[p][1] + br4.y);
            eq.z = fast_exp(aQ[p][2] + br4.z); eq.w = fast_exp(aQ[p][3] + br4.w);
            vv.x = fmaxf(aV[p][0] + bv4.x, 0.f); vv.y = fmaxf(aV[p][1] + bv4.y, 0.f);
            vv.z = fmaxf(aV[p][2] + bv4.z, 0.f); vv.w = fmaxf(aV[p][3] + bv4.w, 0.f);
            *(float4*)&g_EP[sp * C_ + 4 * lane] = ep;
            *(float4*)&g_EQ[sp * C_ + 4 * lane] = eq;
            *(float4*)&g_V [sp * C_ + 4 * lane] = vv;
        }
        __syncwarp();
    }
}

// ============================================================================
// knnq body (device fn): exact 36-NN, warp per query — identical to R13
// (paired columns, register top-10, 36-count certificate, bisection merge).
// ============================================================================
#define LLEN 10
#define INFBITS 0x7f800000u

__device__ __forceinline__ void knnq_body(int blk) {
    int lane = threadIdx.x & 31;
    int W = blk * 8 + (threadIdx.x >> 5);
    int q = ((W & 7) << 12) | (W >> 3);       // balance shuffle (bijective)
    int b = q >> 13;

    float4 me = g_pts4[q];
    float qx = me.x, qy = me.y, qz = me.z;
    int cx = min(G_ - 1, max(0, (int)(qx * (float)G_)));
    int cy = min(G_ - 1, max(0, (int)(qy * (float)G_)));
    int cz = min(G_ - 1, max(0, (int)(qz * (float)G_)));

    const float h = 1.0f / (float)G_;
    const int cbase = b * GC_;
    const int pbase = b * N_;

    int clip = ((cx < 2 || cx > G_ - 3) ? 1 : 0)
             + ((cy < 2 || cy > G_ - 3) ? 1 : 0)
             + ((cz < 2 || cz > G_ - 3) ? 1 : 0);
    int r0 = 2 + clip;

    unsigned ld[LLEN];
    int      lp[LLEN];
    float    dth = 1e9f;

    int hwarp = lane >> 4;
    int lj    = lane & 15;

    for (int r = r0; ; r++) {
        #pragma unroll
        for (int s = 0; s < LLEN; s++) { ld[s] = INFBITS; lp[s] = -1; }

        int lox = max(cx - r, 0), hix = min(cx + r, G_ - 1);
        int loy = max(cy - r, 0), hiy = min(cy + r, G_ - 1);
        int loz = max(cz - r, 0), hiz = min(cz + r, G_ - 1);

        float d1 = (lox > 0)      ? (qx - (float)lox * h)        : 1e9f;
        float d2 = (hix < G_ - 1) ? ((float)(hix + 1) * h - qx)  : 1e9f;
        float d3 = (loy > 0)      ? (qy - (float)loy * h)        : 1e9f;
        float d4 = (hiy < G_ - 1) ? ((float)(hiy + 1) * h - qy)  : 1e9f;
        float d5 = (loz > 0)      ? (qz - (float)loz * h)        : 1e9f;
        float d6 = (hiz < G_ - 1) ? ((float)(hiz + 1) * h - qz)  : 1e9f;
        float dmin = fminf(fminf(fminf(d1, d2), fminf(d3, d4)), fminf(d5, d6));
        dth = fminf(dmin * dmin, 1e9f);

        int cnt_near = 0;

        for (int ix = lox; ix <= hix; ix++) {
            int colbase = cbase + (ix * G_) * G_;
            for (int iy0 = loy; iy0 <= hiy; iy0 += 2) {
                int iy = iy0 + hwarp;
                int s0 = 0, len = 0;
                if (iy <= hiy) {
                    int cc = colbase + iy * G_;
                    s0  = g_cellstart[cc + loz];
                    len = g_cellstart[cc + hiz] + g_cellcnt[cc + hiz] - s0;
                }
                int base = pbase + s0;
                int rot = (ix * 3 + iy0 * 5) & 15;
                for (int j = ((lj - rot) & 15); j < len; j += 16) {
                    float4 c = g_pts4[base + j];
                    float dx = c.x - qx, dy = c.y - qy, dz = c.z - qz;
                    float d = fmaf(dz, dz, fmaf(dy, dy, dx * dx));
                    cnt_near += (d <= dth) ? 1 : 0;
                    unsigned db = __float_as_uint(d);
                    if (db < ld[LLEN - 1]) {
                        unsigned cd = db; int cp = base + j;
                        #pragma unroll
                        for (int s = 0; s < LLEN; s++) {
                            unsigned od = ld[s]; int op = lp[s];
                            if (cd < od) { ld[s] = cd; lp[s] = cp; cd = od; cp = op; }
                        }
                    }
                }
            }
        }

        unsigned tot = __reduce_add_sync(0xffffffffu, (unsigned)cnt_near);
        bool all = (lox == 0 && hix == G_ - 1 && loy == 0 && hiy == G_ - 1 &&
                    loz == 0 && hiz == G_ - 1);
        if (tot >= (unsigned)K_ || all) break;
    }

    // bisection for T = 36th smallest distance (uint bit order)
    unsigned lo = __reduce_min_sync(0xffffffffu, ld[0]);
    unsigned hi = __float_as_uint(fminf(dth, 4.0f));
    if (hi < lo) hi = lo;
    int iter = 0;
    while (lo < hi && iter < 34) {
        unsigned mid = lo + ((hi - lo) >> 1);
        int c = 0;
        #pragma unroll
        for (int s = 0; s < LLEN; s++) c += (ld[s] <= mid) ? 1 : 0;
        unsigned tot = __reduce_add_sync(0xffffffffu, (unsigned)c);
        if (tot >= (unsigned)K_) hi = mid; else lo = mid + 1;
        iter++;
    }
    unsigned T = lo;

    // compaction: all d < T, then deterministic slot-major fill of d == T
    unsigned lmlt = (1u << lane) - 1u;
    int base = 0;
    #pragma unroll
    for (int s = 0; s < LLEN; s++) {
        bool p = (ld[s] < T);
        unsigned m = __ballot_sync(0xffffffffu, p);
        if (p) g_nbr[(size_t)q * K_ + base + __popc(m & lmlt)] = lp[s];
        base += __popc(m);
    }
    #pragma unroll
    for (int s = 0; s < LLEN; s++) {
        if (base >= K_) break;
        bool p = (ld[s] == T);
        unsigned m = __ballot_sync(0xffffffffu, p);
        int rk = __popc(m & lmlt);
        if (p && (base + rk) < K_) g_nbr[(size_t)q * K_ + base + rk] = lp[s];
        base += __popc(m);
    }
}

// ============================================================================
// FUSED kernel: blocks [0, KNN_BLOCKS) run knnq (ALU-bound), blocks
// [KNN_BLOCKS, KNN_BLOCKS+PREP_BLOCKS) run prep (FMA-bound). Independent
// work on complementary pipes -> prep hides under knnq.
// ============================================================================
__global__ __launch_bounds__(256) void knnq_prep_kernel(
        const float* __restrict__ feat, const float* __restrict__ xyz,
        const float* __restrict__ br,   const float* __restrict__ bv) {
    extern __shared__ float sPre[];     // 8 warps * 4 pts * 68
    if (blockIdx.x < KNN_BLOCKS) {
        knnq_body(blockIdx.x);
    } else {
        prep_body(blockIdx.x - KNN_BLOCKS, feat, xyz, br, bv, sPre);
    }
}

// ============================================================================
// Kernel: vector attention accumulate (warp/query, 256 threads).
// ============================================================================
__global__ void attn_kernel() {
    int gw   = (blockIdx.x * blockDim.x + threadIdx.x) >> 5;
    int lane = threadIdx.x & 31;
    if (gw >= BN_) return;
    size_t q = (size_t)gw;

    float4 eq = *(const float4*)&g_EQ[q * C_ + 4 * lane];
    int i0 = g_nbr[q * K_ + lane];
    int i1 = (lane < K_ - 32) ? g_nbr[q * K_ + 32 + lane] : 0;

    float4 acc = make_float4(0.f, 0.f, 0.f, 0.f);
    #pragma unroll 4
    for (int k = 0; k < K_; k++) {
        int j = (k < 32) ? __shfl_sync(0xffffffffu, i0, k)
                         : __shfl_sync(0xffffffffu, i1, k - 32);
        float4 ep = *(const float4*)&g_EP[(size_t)j * C_ + 4 * lane];
        float4 v  = *(const float4*)&g_V [(size_t)j * C_ + 4 * lane];
        float wx = ep.x * eq.x, wy = ep.y * eq.y, wz = ep.z * eq.z, ww = ep.w * eq.w;
        float part = (wx + wy) + (wz + ww);
        part += __shfl_xor_sync(0xffffffffu, part, 16);
        part += __shfl_xor_sync(0xffffffffu, part, 8);
        part += __shfl_xor_sync(0xffffffffu, part, 4);
        part += __shfl_xor_sync(0xffffffffu, part, 2);
        part += __shfl_xor_sync(0xffffffffu, part, 1);
        float rinv = __fdividef(1.0f, part);
        acc.x = fmaf(v.x, wx * rinv, acc.x);
        acc.y = fmaf(v.y, wy * rinv, acc.y);
        acc.z = fmaf(v.z, wz * rinv, acc.z);
        acc.w = fmaf(v.w, ww * rinv, acc.w);
    }
    *(float4*)&g_mid[q * C_ + 4 * lane] = acc;
}

// ============================================================================
// Kernel: output projection  out[pid[q]] = mid[q] @ Ws^T + bs.
// ============================================================================
#define WS_STRIDE 132
#define OUT_SMEM  ((C_ * WS_STRIDE + 8 * C_ * 9) * 4)

__global__ void outproj_kernel(const float* __restrict__ Ws,
                               const float* __restrict__ bs,
                               float* __restrict__ out) {
    extern __shared__ float sm[];
    float* sWs  = sm;                    // [c][d] stride WS_STRIDE
    float* sMid = sm + C_ * WS_STRIDE;   // [warp][c][9]

    int t = threadIdx.x, w = t >> 5, lane = t & 31;
    for (int i = t; i < C_ * C_; i += 256) {
        int d = i >> 7, c = i & 127;
        sWs[c * WS_STRIDE + d] = Ws[i];
    }
    __syncthreads();

    float4 bs4 = *(const float4*)&bs[4 * lane];
    float* smw = sMid + w * C_ * 9;
    int gw = blockIdx.x * 8 + w;                 // 2048 warps total

    for (int itq = 0; itq < 2; itq++) {
        int q0 = (gw + itq * 2048) * 8;
        #pragma unroll
        for (int p = 0; p < 8; p++) {
            float4 m4 = *(const float4*)&g_mid[(size_t)(q0 + p) * C_ + 4 * lane];
            smw[(4 * lane + 0) * 9 + p] = m4.x;
            smw[(4 * lane + 1) * 9 + p] = m4.y;
            smw[(4 * lane + 2) * 9 + p] = m4.z;
            smw[(4 * lane + 3) * 9 + p] = m4.w;
        }
        __syncwarp();
        float4 acc[8];
        #pragma unroll
        for (int p = 0; p < 8; p++) acc[p] = bs4;
        for (int c = 0; c < C_; c++) {
            float4 wr = *(float4*)&sWs[c * WS_STRIDE + 4 * lane];
            #pragma unroll
            for (int p = 0; p < 8; p++) {
                float mc = smw[c * 9 + p];
                acc[p].x = fmaf(wr.x, mc, acc[p].x);
                acc[p].y = fmaf(wr.y, mc, acc[p].y);
                acc[p].z = fmaf(wr.z, mc, acc[p].z);
                acc[p].w = fmaf(wr.w, mc, acc[p].w);
            }
        }
        #pragma unroll
        for (int p = 0; p < 8; p++) {
            size_t row = (size_t)g_pid[q0 + p];     // back to original order
            *(float4*)&out[row * C_ + 4 * lane] = acc[p];
        }
        __syncwarp();
    }
}

// ============================================================================
extern "C" void kernel_launch(void* const* d_in, const int* in_sizes, int n_in,
                              void* d_out, int out_size) {
    const float* feat = (const float*)d_in[0];
    const float* xyz  = (const float*)d_in[1];
    const float* Wr   = (const float*)d_in[2];
    const float* br   = (const float*)d_in[3];
    const float* Wv   = (const float*)d_in[4];
    const float* bv   = (const float*)d_in[5];
    const float* Ws   = (const float*)d_in[6];
    const float* bs   = (const float*)d_in[7];
    float* out = (float*)d_out;

    cudaFuncSetAttribute(outproj_kernel, cudaFuncAttributeMaxDynamicSharedMemorySize, OUT_SMEM);

    void* ccnt;
    cudaGetSymbolAddress(&ccnt, g_cellcnt);
    cudaMemsetAsync(ccnt, 0, B_ * GC_ * sizeof(int));

    // weight transpose (independent of build; cheap)
    wxpose_kernel<<<(DPRE * C_ + 255) / 256, 256>>>(Wr, Wv);

    // grid build (R5 pipeline)
    cellassign_kernel<<<BN_ / 256, 256>>>(xyz);
    scan_kernel<<<B_, 1024>>>();
    scatter_kernel<<<BN_ / 256, 256>>>(xyz);
    sortfix_kernel<<<B_ * GC_ / 256, 256>>>();

    // FUSED: exact 36-NN (ALU-bound) + per-point EP/EQ/V (FMA-bound)
    knnq_prep_kernel<<<KNN_BLOCKS + PREP_BLOCKS, 256, FUSED_SMEM>>>(feat, xyz, br, bv);

    // vector attention accumulate
    attn_kernel<<<BN_ / 8, 256>>>();

    // output projection (+ scatter back to original order)
    outproj_kernel<<<256, 256, OUT_SMEM>>>(Ws, bs, out);
}

// round 15
// speedup vs baseline: 1.3147x; 1.3147x over previous
#include <cuda_runtime.h>
#include <cuda_bf16.h>
#include <math_constants.h>

// Problem constants (fixed by setup_inputs)
#define B_   4
#define N_   8192
#define BN_  (B_ * N_)      // 32768 points
#define DIN  64
#define DPRE 67             // feature(64) + xyz(3)
#define C_   128            // D_OUT
#define K_   36

// spatial grid
#define G_   16
#define GC_  (G_ * G_ * G_)   // 4096 cells per batch

// ---------------- device scratch (no allocations allowed) ----------------
__device__ float  g_EP [BN_ * C_];   // exp(Wr_left @ pre)           (sorted order)
__device__ float  g_EQ [BN_ * C_];   // exp((Wr_r - Wr_l) @ pre + br)(sorted order)
__device__ float  g_V  [BN_ * C_];   // relu(Wv @ pre + bv)          (sorted order)
__device__ float  g_mid[BN_ * C_];   // attention output             (sorted order)
__device__ int    g_nbr[BN_ * K_];   // knn neighbor SORTED positions
__device__ int    g_cellcnt [B_ * GC_];
__device__ int    g_cellstart[B_ * GC_];
__device__ int    g_cellid[BN_];     // per original point: within-batch cell
__device__ int    g_rank  [BN_];     // atomic rank within cell (pre-sort)
__device__ float4 g_pts4 [BN_];      // sorted points (x,y,z,pad)
__device__ int    g_pid  [BN_];      // sorted pos -> original global id
__device__ int    g_spos [BN_];      // original global id -> sorted pos

// ---------------- fast exp (FMA pipe) ------------------------------------
__device__ __forceinline__ float fast_exp(float x) {
    float y = x * 1.4426950408889634f;      // x * log2(e)
    int   e = __float2int_rn(y);
    float f = y - (float)e;                 // f in [-0.5, 0.5]
    float p =            1.5403530393381609e-4f;
    p = fmaf(p, f, 1.3333558146428443e-3f);
    p = fmaf(p, f, 9.6181291076284770e-3f);
    p = fmaf(p, f, 5.5504108664821580e-2f);
    p = fmaf(p, f, 2.4022650695910070e-1f);
    p = fmaf(p, f, 6.9314718055994530e-1f);
    p = fmaf(p, f, 1.0f);
    float s = __int_as_float((e + 127) << 23);
    return p * s;
}

// ============================================================================
// Grid build (R5 pipeline — proven fastest config)
// ============================================================================
__global__ void cellassign_kernel(const float* __restrict__ xyz) {
    int m = blockIdx.x * blockDim.x + threadIdx.x;
    if (m >= BN_) return;
    int b = m >> 13;
    float x = xyz[(size_t)m * 3 + 0];
    float y = xyz[(size_t)m * 3 + 1];
    float z = xyz[(size_t)m * 3 + 2];
    int cx = min(G_ - 1, max(0, (int)(x * (float)G_)));
    int cy = min(G_ - 1, max(0, (int)(y * (float)G_)));
    int cz = min(G_ - 1, max(0, (int)(z * (float)G_)));
    int cell = (cx * G_ + cy) * G_ + cz;
    int r = atomicAdd(&g_cellcnt[b * GC_ + cell], 1);
    g_cellid[m] = cell;
    g_rank[m] = r;
}

__global__ void scan_kernel() {
    __shared__ int s[1024];
    int b = blockIdx.x;
    int t = threadIdx.x;
    int c0 = g_cellcnt[b * GC_ + 4 * t + 0];
    int c1 = g_cellcnt[b * GC_ + 4 * t + 1];
    int c2 = g_cellcnt[b * GC_ + 4 * t + 2];
    int c3 = g_cellcnt[b * GC_ + 4 * t + 3];
    int tot = c0 + c1 + c2 + c3;
    s[t] = tot;
    __syncthreads();
    for (int off = 1; off < 1024; off <<= 1) {
        int x = (t >= off) ? s[t - off] : 0;
        __syncthreads();
        s[t] += x;
        __syncthreads();
    }
    int excl = s[t] - tot;
    g_cellstart[b * GC_ + 4 * t + 0] = excl;
    g_cellstart[b * GC_ + 4 * t + 1] = excl + c0;
    g_cellstart[b * GC_ + 4 * t + 2] = excl + c0 + c1;
    g_cellstart[b * GC_ + 4 * t + 3] = excl + c0 + c1 + c2;
}

__global__ void scatter_kernel(const float* __restrict__ xyz) {
    int m = blockIdx.x * blockDim.x + threadIdx.x;
    if (m >= BN_) return;
    int b = m >> 13;
    int cell = g_cellid[m];
    int p = b * N_ + g_cellstart[b * GC_ + cell] + g_rank[m];
    float x = xyz[(size_t)m * 3 + 0];
    float y = xyz[(size_t)m * 3 + 1];
    float z = xyz[(size_t)m * 3 + 2];
    g_pts4[p] = make_float4(x, y, z, 0.0f);
    g_pid[p] = m;
}

__global__ void sortfix_kernel() {
    int i = blockIdx.x * blockDim.x + threadIdx.x;
    if (i >= B_ * GC_) return;
    int b = i / GC_;
    int cell = i - b * GC_;
    int start = b * N_ + g_cellstart[b * GC_ + cell];
    int cnt = g_cellcnt[b * GC_ + cell];
    for (int a = 1; a < cnt; a++) {
        int pid = g_pid[start + a];
        float4 pt = g_pts4[start + a];
        int j = a - 1;
        while (j >= 0 && g_pid[start + j] > pid) {
            g_pid[start + j + 1]  = g_pid[start + j];
            g_pts4[start + j + 1] = g_pts4[start + j];
            j--;
        }
        g_pid[start + j + 1]  = pid;
        g_pts4[start + j + 1] = pt;
    }
    for (int a = 0; a < cnt; a++) g_spos[g_pid[start + a]] = start + a;
}

// ============================================================================
// Kernel: per-point preprocessing (EP/EQ/V), written in SORTED order.
// ============================================================================
#define PREP_SMEM ((3 * DPRE * C_ + 4 * 4 * 68) * 4)

__global__ void prep_kernel(const float* __restrict__ feat,
                            const float* __restrict__ xyz,
                            const float* __restrict__ Wr,
                            const float* __restrict__ br,
                            const float* __restrict__ Wv,
                            const float* __restrict__ bv) {
    extern __shared__ float sm[];
    float* sWA = sm;                       // Wr_left   [d][c]
    float* sWB = sm + DPRE * C_;           // Wr_right  [d][c] (then -= left)
    float* sWC = sm + 2 * DPRE * C_;       // Wv        [d][c]
    float* sPre = sm + 3 * DPRE * C_;      // [warp][4][68]

    int t = threadIdx.x;
    for (int i = t; i < C_ * 134; i += 128) {
        int c = i / 134, dd = i % 134;
        float v = Wr[i];
        if (dd < DPRE) sWA[dd * C_ + c] = v;
        else           sWB[(dd - DPRE) * C_ + c] = v;
    }
    for (int i = t; i < C_ * DPRE; i += 128) {
        int c = i / DPRE, d = i % DPRE;
        sWC[d * C_ + c] = Wv[i];
    }
    __syncthreads();
    for (int i = t; i < DPRE * C_; i += 128) sWB[i] -= sWA[i];
    __syncthreads();

    int w = t >> 5, lane = t & 31;
    float4 br4 = *(const float4*)&br[4 * lane];
    float4 bv4 = *(const float4*)&bv[4 * lane];
    float* spw = sPre + w * 4 * 68;

    int base = blockIdx.x * 128 + w * 32;   // 32 points per warp
    for (int it = 0; it < 8; it++) {
        int m0 = base + it * 4;
        #pragma unroll
        for (int p = 0; p < 4; p++) {
            int m = m0 + p;
            spw[p * 68 + lane]      = feat[(size_t)m * 64 + lane];
            spw[p * 68 + 32 + lane] = feat[(size_t)m * 64 + 32 + lane];
            if (lane < 3) spw[p * 68 + 64 + lane] = xyz[(size_t)m * 3 + lane];
        }
        __syncwarp();

        float aP[4][4], aQ[4][4], aV[4][4];
        #pragma unroll
        for (int p = 0; p < 4; p++)
            #pragma unroll
            for (int r = 0; r < 4; r++) { aP[p][r] = 0.f; aQ[p][r] = 0.f; aV[p][r] = 0.f; }

        for (int d = 0; d < DPRE; d++) {
            float4 wa = *(float4*)&sWA[d * C_ + 4 * lane];
            float4 wb = *(float4*)&sWB[d * C_ + 4 * lane];
            float4 wc = *(float4*)&sWC[d * C_ + 4 * lane];
            #pragma unroll
            for (int p = 0; p < 4; p++) {
                float x = spw[p * 68 + d];
                aP[p][0] = fmaf(wa.x, x, aP[p][0]);
                aP[p][1] = fmaf(wa.y, x, aP[p][1]);
                aP[p][2] = fmaf(wa.z, x, aP[p][2]);
                aP[p][3] = fmaf(wa.w, x, aP[p][3]);
                aQ[p][0] = fmaf(wb.x, x, aQ[p][0]);
                aQ[p][1] = fmaf(wb.y, x, aQ[p][1]);
                aQ[p][2] = fmaf(wb.z, x, aQ[p][2]);
                aQ[p][3] = fmaf(wb.w, x, aQ[p][3]);
                aV[p][0] = fmaf(wc.x, x, aV[p][0]);
                aV[p][1] = fmaf(wc.y, x, aV[p][1]);
                aV[p][2] = fmaf(wc.z, x, aV[p][2]);
                aV[p][3] = fmaf(wc.w, x, aV[p][3]);
            }
        }
        #pragma unroll
        for (int p = 0; p < 4; p++) {
            size_t sp = (size_t)g_spos[m0 + p];     // sorted destination
            float4 ep, eq, vv;
            ep.x = fast_exp(aP[p][0]); ep.y = fast_exp(aP[p][1]);
            ep.z = fast_exp(aP[p][2]); ep.w = fast_exp(aP[p][3]);
            eq.x = fast_exp(aQ[p][0] + br4.x); eq.y = fast_exp(aQ[p][1] + br4.y);
            eq.z = fast_exp(aQ[p][2] + br4.z); eq.w = fast_exp(aQ[p][3] + br4.w);
            vv.x = fmaxf(aV[p][0] + bv4.x, 0.f); vv.y = fmaxf(aV[p][1] + bv4.y, 0.f);
            vv.z = fmaxf(aV[p][2] + bv4.z, 0.f); vv.w = fmaxf(aV[p][3] + bv4.w, 0.f);
            *(float4*)&g_EP[sp * C_ + 4 * lane] = ep;
            *(float4*)&g_EQ[sp * C_ + 4 * lane] = eq;
            *(float4*)&g_V [sp * C_ + 4 * lane] = vv;
        }
        __syncwarp();
    }
}

// ============================================================================
// Kernel: exact 36-NN, WARP PER QUERY (R13 structure).
// CHANGE vs R13: the top-10 list insert is gated on d <= dth. Since the
// selection threshold T always satisfies T <= dth (36-count certificate; in
// the full-grid case dth = 1e9), candidates beyond dth can never be output —
// the gate is output-bit-identical and skips most insert-chain executions.
// ============================================================================
#define LLEN 10
#define INFBITS 0x7f800000u

__global__ void knnq_kernel() {
    int lane = threadIdx.x & 31;
    int W = blockIdx.x * (blockDim.x >> 5) + (threadIdx.x >> 5);
    int q = ((W & 7) << 12) | (W >> 3);       // balance shuffle (bijective)
    int b = q >> 13;

    float4 me = g_pts4[q];
    float qx = me.x, qy = me.y, qz = me.z;
    int cx = min(G_ - 1, max(0, (int)(qx * (float)G_)));
    int cy = min(G_ - 1, max(0, (int)(qy * (float)G_)));
    int cz = min(G_ - 1, max(0, (int)(qz * (float)G_)));

    const float h = 1.0f / (float)G_;
    const int cbase = b * GC_;
    const int pbase = b * N_;

    int clip = ((cx < 2 || cx > G_ - 3) ? 1 : 0)
             + ((cy < 2 || cy > G_ - 3) ? 1 : 0)
             + ((cz < 2 || cz > G_ - 3) ? 1 : 0);
    int r0 = 2 + clip;

    unsigned ld[LLEN];
    int      lp[LLEN];
    float    dth = 1e9f;

    int hwarp = lane >> 4;      // which column of the pair
    int lj    = lane & 15;      // index within half-warp

    for (int r = r0; ; r++) {
        #pragma unroll
        for (int s = 0; s < LLEN; s++) { ld[s] = INFBITS; lp[s] = -1; }

        int lox = max(cx - r, 0), hix = min(cx + r, G_ - 1);
        int loy = max(cy - r, 0), hiy = min(cy + r, G_ - 1);
        int loz = max(cz - r, 0), hiz = min(cz + r, G_ - 1);

        float d1 = (lox > 0)      ? (qx - (float)lox * h)        : 1e9f;
        float d2 = (hix < G_ - 1) ? ((float)(hix + 1) * h - qx)  : 1e9f;
        float d3 = (loy > 0)      ? (qy - (float)loy * h)        : 1e9f;
        float d4 = (hiy < G_ - 1) ? ((float)(hiy + 1) * h - qy)  : 1e9f;
        float d5 = (loz > 0)      ? (qz - (float)loz * h)        : 1e9f;
        float d6 = (hiz < G_ - 1) ? ((float)(hiz + 1) * h - qz)  : 1e9f;
        float dmin = fminf(fminf(fminf(d1, d2), fminf(d3, d4)), fminf(d5, d6));
        dth = fminf(dmin * dmin, 1e9f);

        int cnt_near = 0;

        for (int ix = lox; ix <= hix; ix++) {
            int colbase = cbase + (ix * G_) * G_;
            for (int iy0 = loy; iy0 <= hiy; iy0 += 2) {
                int iy = iy0 + hwarp;
                int s0 = 0, len = 0;
                if (iy <= hiy) {
                    int cc = colbase + iy * G_;
                    s0  = g_cellstart[cc + loz];
                    len = g_cellstart[cc + hiz] + g_cellcnt[cc + hiz] - s0;
                }
                int base = pbase + s0;
                int rot = (ix * 3 + iy0 * 5) & 15;   // de-skew lane<->j mapping
                for (int j = ((lj - rot) & 15); j < len; j += 16) {
                    float4 c = g_pts4[base + j];
                    float dx = c.x - qx, dy = c.y - qy, dz = c.z - qz;
                    float d = fmaf(dz, dz, fmaf(dy, dy, dx * dx));
                    if (d <= dth) {                        // relevance gate
                        cnt_near++;
                        unsigned db = __float_as_uint(d);
                        if (db < ld[LLEN - 1]) {
                            unsigned cd = db; int cp = base + j;
                            #pragma unroll
                            for (int s = 0; s < LLEN; s++) {
                                unsigned od = ld[s]; int op = lp[s];
                                if (cd < od) { ld[s] = cd; lp[s] = cp; cd = od; cp = op; }
                            }
                        }
                    }
                }
            }
        }

        unsigned tot = __reduce_add_sync(0xffffffffu, (unsigned)cnt_near);
        bool all = (lox == 0 && hix == G_ - 1 && loy == 0 && hiy == G_ - 1 &&
                    loz == 0 && hiz == G_ - 1);
        if (tot >= (unsigned)K_ || all) break;
    }

    // ---- merge: bisection for T = 36th smallest distance (as uint bits) ----
    unsigned lo = __reduce_min_sync(0xffffffffu, ld[0]);
    unsigned hi = __float_as_uint(fminf(dth, 4.0f));   // certificate: count(<=dth)>=36
    if (hi < lo) hi = lo;
    int iter = 0;
    while (lo < hi && iter < 34) {
        unsigned mid = lo + ((hi - lo) >> 1);
        int c = 0;
        #pragma unroll
        for (int s = 0; s < LLEN; s++) c += (ld[s] <= mid) ? 1 : 0;
        unsigned tot = __reduce_add_sync(0xffffffffu, (unsigned)c);
        if (tot >= (unsigned)K_) hi = mid; else lo = mid + 1;
        iter++;
    }
    unsigned T = lo;

    // ---- compaction: all d < T, then fill to 36 with d == T (slot-major) ----
    unsigned lmlt = (1u << lane) - 1u;
    int base = 0;
    #pragma unroll
    for (int s = 0; s < LLEN; s++) {
        bool p = (ld[s] < T);
        unsigned m = __ballot_sync(0xffffffffu, p);
        if (p) g_nbr[(size_t)q * K_ + base + __popc(m & lmlt)] = lp[s];
        base += __popc(m);
    }
    #pragma unroll
    for (int s = 0; s < LLEN; s++) {
        if (base >= K_) break;                 // warp-uniform
        bool p = (ld[s] == T);
        unsigned m = __ballot_sync(0xffffffffu, p);
        int rk = __popc(m & lmlt);
        if (p && (base + rk) < K_) g_nbr[(size_t)q * K_ + base + rk] = lp[s];
        base += __popc(m);
    }
}

// ============================================================================
// Kernel: vector attention accumulate (warp/query, 256 threads).
// ============================================================================
__global__ void attn_kernel() {
    int gw   = (blockIdx.x * blockDim.x + threadIdx.x) >> 5;
    int lane = threadIdx.x & 31;
    if (gw >= BN_) return;
    size_t q = (size_t)gw;

    float4 eq = *(const float4*)&g_EQ[q * C_ + 4 * lane];
    int i0 = g_nbr[q * K_ + lane];
    int i1 = (lane < K_ - 32) ? g_nbr[q * K_ + 32 + lane] : 0;

    float4 acc = make_float4(0.f, 0.f, 0.f, 0.f);
    #pragma unroll 4
    for (int k = 0; k < K_; k++) {
        int j = (k < 32) ? __shfl_sync(0xffffffffu, i0, k)
                         : __shfl_sync(0xffffffffu, i1, k - 32);
        float4 ep = *(const float4*)&g_EP[(size_t)j * C_ + 4 * lane];
        float4 v  = *(const float4*)&g_V [(size_t)j * C_ + 4 * lane];
        float wx = ep.x * eq.x, wy = ep.y * eq.y, wz = ep.z * eq.z, ww = ep.w * eq.w;
        float part = (wx + wy) + (wz + ww);
        part += __shfl_xor_sync(0xffffffffu, part, 16);
        part += __shfl_xor_sync(0xffffffffu, part, 8);
        part += __shfl_xor_sync(0xffffffffu, part, 4);
        part += __shfl_xor_sync(0xffffffffu, part, 2);
        part += __shfl_xor_sync(0xffffffffu, part, 1);
        float rinv = __fdividef(1.0f, part);
        acc.x = fmaf(v.x, wx * rinv, acc.x);
        acc.y = fmaf(v.y, wy * rinv, acc.y);
        acc.z = fmaf(v.z, wz * rinv, acc.z);
        acc.w = fmaf(v.w, ww * rinv, acc.w);
    }
    *(float4*)&g_mid[q * C_ + 4 * lane] = acc;
}

// ============================================================================
// Kernel: output projection  out[pid[q]] = mid[q] @ Ws^T + bs.
// ============================================================================
#define WS_STRIDE 132
#define OUT_SMEM  ((C_ * WS_STRIDE + 8 * C_ * 9) * 4)

__global__ void outproj_kernel(const float* __restrict__ Ws,
                               const float* __restrict__ bs,
                               float* __restrict__ out) {
    extern __shared__ float sm[];
    float* sWs  = sm;                    // [c][d] stride WS_STRIDE
    float* sMid = sm + C_ * WS_STRIDE;   // [warp][c][9]

    int t = threadIdx.x, w = t >> 5, lane = t & 31;
    for (int i = t; i < C_ * C_; i += 256) {
        int d = i >> 7, c = i & 127;
        sWs[c * WS_STRIDE + d] = Ws[i];
    }
    __syncthreads();

    float4 bs4 = *(const float4*)&bs[4 * lane];
    float* smw = sMid + w * C_ * 9;
    int gw = blockIdx.x * 8 + w;                 // 2048 warps total

    for (int itq = 0; itq < 2; itq++) {
        int q0 = (gw + itq * 2048) * 8;
        #pragma unroll
        for (int p = 0; p < 8; p++) {
            float4 m4 = *(const float4*)&g_mid[(size_t)(q0 + p) * C_ + 4 * lane];
            smw[(4 * lane + 0) * 9 + p] = m4.x;
            smw[(4 * lane + 1) * 9 + p] = m4.y;
            smw[(4 * lane + 2) * 9 + p] = m4.z;
            smw[(4 * lane + 3) * 9 + p] = m4.w;
        }
        __syncwarp();
        float4 acc[8];
        #pragma unroll
        for (int p = 0; p < 8; p++) acc[p] = bs4;
        for (int c = 0; c < C_; c++) {
            float4 wr = *(float4*)&sWs[c * WS_STRIDE + 4 * lane];
            #pragma unroll
            for (int p = 0; p < 8; p++) {
                float mc = smw[c * 9 + p];
                acc[p].x = fmaf(wr.x, mc, acc[p].x);
                acc[p].y = fmaf(wr.y, mc, acc[p].y);
                acc[p].z = fmaf(wr.z, mc, acc[p].z);
                acc[p].w = fmaf(wr.w, mc, acc[p].w);
            }
        }
        #pragma unroll
        for (int p = 0; p < 8; p++) {
            size_t row = (size_t)g_pid[q0 + p];     // back to original order
            *(float4*)&out[row * C_ + 4 * lane] = acc[p];
        }
        __syncwarp();
    }
}

// ============================================================================
extern "C" void kernel_launch(void* const* d_in, const int* in_sizes, int n_in,
                              void* d_out, int out_size) {
    const float* feat = (const float*)d_in[0];
    const float* xyz  = (const float*)d_in[1];
    const float* Wr   = (const float*)d_in[2];
    const float* br   = (const float*)d_in[3];
    const float* Wv   = (const float*)d_in[4];
    const float* bv   = (const float*)d_in[5];
    const float* Ws   = (const float*)d_in[6];
    const float* bs   = (const float*)d_in[7];
    float* out = (float*)d_out;

    cudaFuncSetAttribute(prep_kernel, cudaFuncAttributeMaxDynamicSharedMemorySize, PREP_SMEM);
    cudaFuncSetAttribute(outproj_kernel, cudaFuncAttributeMaxDynamicSharedMemorySize, OUT_SMEM);

    void* ccnt;
    cudaGetSymbolAddress(&ccnt, g_cellcnt);
    cudaMemsetAsync(ccnt, 0, B_ * GC_ * sizeof(int));

    // grid build (R5 pipeline)
    cellassign_kernel<<<BN_ / 256, 256>>>(xyz);
    scan_kernel<<<B_, 1024>>>();
    scatter_kernel<<<BN_ / 256, 256>>>(xyz);
    sortfix_kernel<<<B_ * GC_ / 256, 256>>>();

    // per-point EP/EQ/V (written in sorted order)
    prep_kernel<<<BN_ / 128, 128, PREP_SMEM>>>(feat, xyz, Wr, br, Wv, bv);

    // exact 36-NN, warp per query (paired columns + gated insert + bisection)
    knnq_kernel<<<BN_ / 8, 256>>>();

    // vector attention accumulate
    attn_kernel<<<BN_ / 8, 256>>>();

    // output projection (+ scatter back to original order)
    outproj_kernel<<<256, 256, OUT_SMEM>>>(Ws, bs, out);
}

// round 16
// speedup vs baseline: 1.3836x; 1.0524x over previous
#include <cuda_runtime.h>
#include <cuda_bf16.h>
#include <math_constants.h>

// Problem constants (fixed by setup_inputs)
#define B_   4
#define N_   8192
#define BN_  (B_ * N_)      // 32768 points
#define DIN  64
#define DPRE 67             // feature(64) + xyz(3)
#define C_   128            // D_OUT
#define K_   36

// spatial grid
#define G_   16
#define GC_  (G_ * G_ * G_)   // 4096 cells per batch

// ---------------- device scratch (no allocations allowed) ----------------
__device__ float  g_EP [BN_ * C_];   // exp(Wr_left @ pre)           (sorted order)
__device__ float  g_EQ [BN_ * C_];   // exp((Wr_r - Wr_l) @ pre + br)(sorted order)
__device__ float  g_V  [BN_ * C_];   // relu(Wv @ pre + bv)          (sorted order)
__device__ float  g_mid[BN_ * C_];   // attention output             (sorted order)
__device__ int    g_nbr[BN_ * K_];   // knn neighbor SORTED positions
__device__ int    g_cellcnt [B_ * GC_];
__device__ int    g_cellstart[B_ * GC_];
__device__ int    g_cellid[BN_];     // per original point: within-batch cell
__device__ int    g_rank  [BN_];     // atomic rank within cell (pre-sort)
__device__ float4 g_pts4 [BN_];      // sorted points (x,y,z,pad)
__device__ int    g_pid  [BN_];      // sorted pos -> original global id
__device__ int    g_spos [BN_];      // original global id -> sorted pos

// ---------------- fast exp (FMA pipe) ------------------------------------
__device__ __forceinline__ float fast_exp(float x) {
    float y = x * 1.4426950408889634f;      // x * log2(e)
    int   e = __float2int_rn(y);
    float f = y - (float)e;                 // f in [-0.5, 0.5]
    float p =            1.5403530393381609e-4f;
    p = fmaf(p, f, 1.3333558146428443e-3f);
    p = fmaf(p, f, 9.6181291076284770e-3f);
    p = fmaf(p, f, 5.5504108664821580e-2f);
    p = fmaf(p, f, 2.4022650695910070e-1f);
    p = fmaf(p, f, 6.9314718055994530e-1f);
    p = fmaf(p, f, 1.0f);
    float s = __int_as_float((e + 127) << 23);
    return p * s;
}

// ============================================================================
// Grid build (R5 pipeline; sortfix re-gridded to 128 blocks)
// ============================================================================
__global__ void cellassign_kernel(const float* __restrict__ xyz) {
    int m = blockIdx.x * blockDim.x + threadIdx.x;
    if (m >= BN_) return;
    int b = m >> 13;
    float x = xyz[(size_t)m * 3 + 0];
    float y = xyz[(size_t)m * 3 + 1];
    float z = xyz[(size_t)m * 3 + 2];
    int cx = min(G_ - 1, max(0, (int)(x * (float)G_)));
    int cy = min(G_ - 1, max(0, (int)(y * (float)G_)));
    int cz = min(G_ - 1, max(0, (int)(z * (float)G_)));
    int cell = (cx * G_ + cy) * G_ + cz;
    int r = atomicAdd(&g_cellcnt[b * GC_ + cell], 1);
    g_cellid[m] = cell;
    g_rank[m] = r;
}

__global__ void scan_kernel() {
    __shared__ int s[1024];
    int b = blockIdx.x;
    int t = threadIdx.x;
    int c0 = g_cellcnt[b * GC_ + 4 * t + 0];
    int c1 = g_cellcnt[b * GC_ + 4 * t + 1];
    int c2 = g_cellcnt[b * GC_ + 4 * t + 2];
    int c3 = g_cellcnt[b * GC_ + 4 * t + 3];
    int tot = c0 + c1 + c2 + c3;
    s[t] = tot;
    __syncthreads();
    for (int off = 1; off < 1024; off <<= 1) {
        int x = (t >= off) ? s[t - off] : 0;
        __syncthreads();
        s[t] += x;
        __syncthreads();
    }
    int excl = s[t] - tot;
    g_cellstart[b * GC_ + 4 * t + 0] = excl;
    g_cellstart[b * GC_ + 4 * t + 1] = excl + c0;
    g_cellstart[b * GC_ + 4 * t + 2] = excl + c0 + c1;
    g_cellstart[b * GC_ + 4 * t + 3] = excl + c0 + c1 + c2;
}

__global__ void scatter_kernel(const float* __restrict__ xyz) {
    int m = blockIdx.x * blockDim.x + threadIdx.x;
    if (m >= BN_) return;
    int b = m >> 13;
    int cell = g_cellid[m];
    int p = b * N_ + g_cellstart[b * GC_ + cell] + g_rank[m];
    float x = xyz[(size_t)m * 3 + 0];
    float y = xyz[(size_t)m * 3 + 1];
    float z = xyz[(size_t)m * 3 + 2];
    g_pts4[p] = make_float4(x, y, z, 0.0f);
    g_pid[p] = m;
}

__global__ void sortfix_kernel() {
    int i = blockIdx.x * blockDim.x + threadIdx.x;
    if (i >= B_ * GC_) return;
    int b = i / GC_;
    int cell = i - b * GC_;
    int start = b * N_ + g_cellstart[b * GC_ + cell];
    int cnt = g_cellcnt[b * GC_ + cell];
    for (int a = 1; a < cnt; a++) {
        int pid = g_pid[start + a];
        float4 pt = g_pts4[start + a];
        int j = a - 1;
        while (j >= 0 && g_pid[start + j] > pid) {
            g_pid[start + j + 1]  = g_pid[start + j];
            g_pts4[start + j + 1] = g_pts4[start + j];
            j--;
        }
        g_pid[start + j + 1]  = pid;
        g_pts4[start + j + 1] = pt;
    }
    for (int a = 0; a < cnt; a++) g_spos[g_pid[start + a]] = start + a;
}

// ============================================================================
// Kernel: per-point preprocessing (EP/EQ/V), written in SORTED order.
// CHANGE vs R15: 256-thread blocks (8 warps share one smem weight copy),
// grid 128. Per-warp instruction stream unchanged -> bit-identical output,
// ~2x resident warps per SM for the FMA-latency chain.
// ============================================================================
#define PREP_WARPS 8
#define PREP_SMEM ((3 * DPRE * C_ + PREP_WARPS * 4 * 68) * 4)

__global__ void prep_kernel(const float* __restrict__ feat,
                            const float* __restrict__ xyz,
                            const float* __restrict__ Wr,
                            const float* __restrict__ br,
                            const float* __restrict__ Wv,
                            const float* __restrict__ bv) {
    extern __shared__ float sm[];
    float* sWA = sm;                       // Wr_left   [d][c]
    float* sWB = sm + DPRE * C_;           // Wr_right  [d][c] (then -= left)
    float* sWC = sm + 2 * DPRE * C_;       // Wv        [d][c]
    float* sPre = sm + 3 * DPRE * C_;      // [warp][4][68]

    int t = threadIdx.x;
    for (int i = t; i < C_ * 134; i += 256) {
        int c = i / 134, dd = i % 134;
        float v = Wr[i];
        if (dd < DPRE) sWA[dd * C_ + c] = v;
        else           sWB[(dd - DPRE) * C_ + c] = v;
    }
    for (int i = t; i < C_ * DPRE; i += 256) {
        int c = i / DPRE, d = i % DPRE;
        sWC[d * C_ + c] = Wv[i];
    }
    __syncthreads();
    for (int i = t; i < DPRE * C_; i += 256) sWB[i] -= sWA[i];
    __syncthreads();

    int w = t >> 5, lane = t & 31;
    float4 br4 = *(const float4*)&br[4 * lane];
    float4 bv4 = *(const float4*)&bv[4 * lane];
    float* spw = sPre + w * 4 * 68;

    int base = blockIdx.x * 256 + w * 32;   // 32 points per warp
    for (int it = 0; it < 8; it++) {
        int m0 = base + it * 4;
        #pragma unroll
        for (int p = 0; p < 4; p++) {
            int m = m0 + p;
            spw[p * 68 + lane]      = feat[(size_t)m * 64 + lane];
            spw[p * 68 + 32 + lane] = feat[(size_t)m * 64 + 32 + lane];
            if (lane < 3) spw[p * 68 + 64 + lane] = xyz[(size_t)m * 3 + lane];
        }
        __syncwarp();

        float aP[4][4], aQ[4][4], aV[4][4];
        #pragma unroll
        for (int p = 0; p < 4; p++)
            #pragma unroll
            for (int r = 0; r < 4; r++) { aP[p][r] = 0.f; aQ[p][r] = 0.f; aV[p][r] = 0.f; }

        for (int d = 0; d < DPRE; d++) {
            float4 wa = *(float4*)&sWA[d * C_ + 4 * lane];
            float4 wb = *(float4*)&sWB[d * C_ + 4 * lane];
            float4 wc = *(float4*)&sWC[d * C_ + 4 * lane];
            #pragma unroll
            for (int p = 0; p < 4; p++) {
                float x = spw[p * 68 + d];
                aP[p][0] = fmaf(wa.x, x, aP[p][0]);
                aP[p][1] = fmaf(wa.y, x, aP[p][1]);
                aP[p][2] = fmaf(wa.z, x, aP[p][2]);
                aP[p][3] = fmaf(wa.w, x, aP[p][3]);
                aQ[p][0] = fmaf(wb.x, x, aQ[p][0]);
                aQ[p][1] = fmaf(wb.y, x, aQ[p][1]);
                aQ[p][2] = fmaf(wb.z, x, aQ[p][2]);
                aQ[p][3] = fmaf(wb.w, x, aQ[p][3]);
                aV[p][0] = fmaf(wc.x, x, aV[p][0]);
                aV[p][1] = fmaf(wc.y, x, aV[p][1]);
                aV[p][2] = fmaf(wc.z, x, aV[p][2]);
                aV[p][3] = fmaf(wc.w, x, aV[p][3]);
            }
        }
        #pragma unroll
        for (int p = 0; p < 4; p++) {
            size_t sp = (size_t)g_spos[m0 + p];     // sorted destination
            float4 ep, eq, vv;
            ep.x = fast_exp(aP[p][0]); ep.y = fast_exp(aP[p][1]);
            ep.z = fast_exp(aP[p][2]); ep.w = fast_exp(aP[p][3]);
            eq.x = fast_exp(aQ[p][0] + br4.x); eq.y = fast_exp(aQ[p][1] + br4.y);
            eq.z = fast_exp(aQ[p][2] + br4.z); eq.w = fast_exp(aQ[p][3] + br4.w);
            vv.x = fmaxf(aV[p][0] + bv4.x, 0.f); vv.y = fmaxf(aV[p][1] + bv4.y, 0.f);
            vv.z = fmaxf(aV[p][2] + bv4.z, 0.f); vv.w = fmaxf(aV[p][3] + bv4.w, 0.f);
            *(float4*)&g_EP[sp * C_ + 4 * lane] = ep;
            *(float4*)&g_EQ[sp * C_ + 4 * lane] = eq;
            *(float4*)&g_V [sp * C_ + 4 * lane] = vv;
        }
        __syncwarp();
    }
}

// ============================================================================
// Kernel: exact 36-NN, WARP PER QUERY.
// CHANGE vs R15: tighter wall-aware initial radius. Box-face distance is
// always >= r*h; required ball radii are 0.128 (half), 0.161 (quarter),
// 0.171 (eighth) => r=3 covers clip 1-2, r=4 covers clip 3. Exactness is
// still guaranteed by the 36-count certificate + rescan loop.
// ============================================================================
#define LLEN 10
#define INFBITS 0x7f800000u

__global__ void knnq_kernel() {
    int lane = threadIdx.x & 31;
    int W = blockIdx.x * (blockDim.x >> 5) + (threadIdx.x >> 5);
    int q = ((W & 7) << 12) | (W >> 3);       // balance shuffle (bijective)
    int b = q >> 13;

    float4 me = g_pts4[q];
    float qx = me.x, qy = me.y, qz = me.z;
    int cx = min(G_ - 1, max(0, (int)(qx * (float)G_)));
    int cy = min(G_ - 1, max(0, (int)(qy * (float)G_)));
    int cz = min(G_ - 1, max(0, (int)(qz * (float)G_)));

    const float h = 1.0f / (float)G_;
    const int cbase = b * GC_;
    const int pbase = b * N_;

    int clip = ((cx < 2 || cx > G_ - 3) ? 1 : 0)
             + ((cy < 2 || cy > G_ - 3) ? 1 : 0)
             + ((cz < 2 || cz > G_ - 3) ? 1 : 0);
    int r0 = (clip == 3) ? 4 : (clip ? 3 : 2);

    unsigned ld[LLEN];
    int      lp[LLEN];
    float    dth = 1e9f;

    int hwarp = lane >> 4;      // which column of the pair
    int lj    = lane & 15;      // index within half-warp

    for (int r = r0; ; r++) {
        #pragma unroll
        for (int s = 0; s < LLEN; s++) { ld[s] = INFBITS; lp[s] = -1; }

        int lox = max(cx - r, 0), hix = min(cx + r, G_ - 1);
        int loy = max(cy - r, 0), hiy = min(cy + r, G_ - 1);
        int loz = max(cz - r, 0), hiz = min(cz + r, G_ - 1);

        float d1 = (lox > 0)      ? (qx - (float)lox * h)        : 1e9f;
        float d2 = (hix < G_ - 1) ? ((float)(hix + 1) * h - qx)  : 1e9f;
        float d3 = (loy > 0)      ? (qy - (float)loy * h)        : 1e9f;
        float d4 = (hiy < G_ - 1) ? ((float)(hiy + 1) * h - qy)  : 1e9f;
        float d5 = (loz > 0)      ? (qz - (float)loz * h)        : 1e9f;
        float d6 = (hiz < G_ - 1) ? ((float)(hiz + 1) * h - qz)  : 1e9f;
        float dmin = fminf(fminf(fminf(d1, d2), fminf(d3, d4)), fminf(d5, d6));
        dth = fminf(dmin * dmin, 1e9f);

        int cnt_near = 0;

        for (int ix = lox; ix <= hix; ix++) {
            int colbase = cbase + (ix * G_) * G_;
            for (int iy0 = loy; iy0 <= hiy; iy0 += 2) {
                int iy = iy0 + hwarp;
                int s0 = 0, len = 0;
                if (iy <= hiy) {
                    int cc = colbase + iy * G_;
                    s0  = g_cellstart[cc + loz];
                    len = g_cellstart[cc + hiz] + g_cellcnt[cc + hiz] - s0;
                }
                int base = pbase + s0;
                int rot = (ix * 3 + iy0 * 5) & 15;   // de-skew lane<->j mapping
                for (int j = ((lj - rot) & 15); j < len; j += 16) {
                    float4 c = g_pts4[base + j];
                    float dx = c.x - qx, dy = c.y - qy, dz = c.z - qz;
                    float d = fmaf(dz, dz, fmaf(dy, dy, dx * dx));
                    if (d <= dth) {                        // relevance gate
                        cnt_near++;
                        unsigned db = __float_as_uint(d);
                        if (db < ld[LLEN - 1]) {
                            unsigned cd = db; int cp = base + j;
                            #pragma unroll
                            for (int s = 0; s < LLEN; s++) {
                                unsigned od = ld[s]; int op = lp[s];
                                if (cd < od) { ld[s] = cd; lp[s] = cp; cd = od; cp = op; }
                            }
                        }
                    }
                }
            }
        }

        unsigned tot = __reduce_add_sync(0xffffffffu, (unsigned)cnt_near);
        bool all = (lox == 0 && hix == G_ - 1 && loy == 0 && hiy == G_ - 1 &&
                    loz == 0 && hiz == G_ - 1);
        if (tot >= (unsigned)K_ || all) break;
    }

    // ---- merge: bisection for T = 36th smallest distance (as uint bits) ----
    unsigned lo = __reduce_min_sync(0xffffffffu, ld[0]);
    unsigned hi = __float_as_uint(fminf(dth, 4.0f));   // certificate: count(<=dth)>=36
    if (hi < lo) hi = lo;
    int iter = 0;
    while (lo < hi && iter < 34) {
        unsigned mid = lo + ((hi - lo) >> 1);
        int c = 0;
        #pragma unroll
        for (int s = 0; s < LLEN; s++) c += (ld[s] <= mid) ? 1 : 0;
        unsigned tot = __reduce_add_sync(0xffffffffu, (unsigned)c);
        if (tot >= (unsigned)K_) hi = mid; else lo = mid + 1;
        iter++;
    }
    unsigned T = lo;

    // ---- compaction: all d < T, then fill to 36 with d == T (slot-major) ----
    unsigned lmlt = (1u << lane) - 1u;
    int base = 0;
    #pragma unroll
    for (int s = 0; s < LLEN; s++) {
        bool p = (ld[s] < T);
        unsigned m = __ballot_sync(0xffffffffu, p);
        if (p) g_nbr[(size_t)q * K_ + base + __popc(m & lmlt)] = lp[s];
        base += __popc(m);
    }
    #pragma unroll
    for (int s = 0; s < LLEN; s++) {
        if (base >= K_) break;                 // warp-uniform
        bool p = (ld[s] == T);
        unsigned m = __ballot_sync(0xffffffffu, p);
        int rk = __popc(m & lmlt);
        if (p && (base + rk) < K_) g_nbr[(size_t)q * K_ + base + rk] = lp[s];
        base += __popc(m);
    }
}

// ============================================================================
// Kernel: vector attention accumulate (warp/query, 256 threads).
// ============================================================================
__global__ void attn_kernel() {
    int gw   = (blockIdx.x * blockDim.x + threadIdx.x) >> 5;
    int lane = threadIdx.x & 31;
    if (gw >= BN_) return;
    size_t q = (size_t)gw;

    float4 eq = *(const float4*)&g_EQ[q * C_ + 4 * lane];
    int i0 = g_nbr[q * K_ + lane];
    int i1 = (lane < K_ - 32) ? g_nbr[q * K_ + 32 + lane] : 0;

    float4 acc = make_float4(0.f, 0.f, 0.f, 0.f);
    #pragma unroll 4
    for (int k = 0; k < K_; k++) {
        int j = (k < 32) ? __shfl_sync(0xffffffffu, i0, k)
                         : __shfl_sync(0xffffffffu, i1, k - 32);
        float4 ep = *(const float4*)&g_EP[(size_t)j * C_ + 4 * lane];
        float4 v  = *(const float4*)&g_V [(size_t)j * C_ + 4 * lane];
        float wx = ep.x * eq.x, wy = ep.y * eq.y, wz = ep.z * eq.z, ww = ep.w * eq.w;
        float part = (wx + wy) + (wz + ww);
        part += __shfl_xor_sync(0xffffffffu, part, 16);
        part += __shfl_xor_sync(0xffffffffu, part, 8);
        part += __shfl_xor_sync(0xffffffffu, part, 4);
        part += __shfl_xor_sync(0xffffffffu, part, 2);
        part += __shfl_xor_sync(0xffffffffu, part, 1);
        float rinv = __fdividef(1.0f, part);
        acc.x = fmaf(v.x, wx * rinv, acc.x);
        acc.y = fmaf(v.y, wy * rinv, acc.y);
        acc.z = fmaf(v.z, wz * rinv, acc.z);
        acc.w = fmaf(v.w, ww * rinv, acc.w);
    }
    *(float4*)&g_mid[q * C_ + 4 * lane] = acc;
}

// ============================================================================
// Kernel: output projection  out[pid[q]] = mid[q] @ Ws^T + bs.
// ============================================================================
#define WS_STRIDE 132
#define OUT_SMEM  ((C_ * WS_STRIDE + 8 * C_ * 9) * 4)

__global__ void outproj_kernel(const float* __restrict__ Ws,
                               const float* __restrict__ bs,
                               float* __restrict__ out) {
    extern __shared__ float sm[];
    float* sWs  = sm;                    // [c][d] stride WS_STRIDE
    float* sMid = sm + C_ * WS_STRIDE;   // [warp][c][9]

    int t = threadIdx.x, w = t >> 5, lane = t & 31;
    for (int i = t; i < C_ * C_; i += 256) {
        int d = i >> 7, c = i & 127;
        sWs[c * WS_STRIDE + d] = Ws[i];
    }
    __syncthreads();

    float4 bs4 = *(const float4*)&bs[4 * lane];
    float* smw = sMid + w * C_ * 9;
    int gw = blockIdx.x * 8 + w;                 // 2048 warps total

    for (int itq = 0; itq < 2; itq++) {
        int q0 = (gw + itq * 2048) * 8;
        #pragma unroll
        for (int p = 0; p < 8; p++) {
            float4 m4 = *(const float4*)&g_mid[(size_t)(q0 + p) * C_ + 4 * lane];
            smw[(4 * lane + 0) * 9 + p] = m4.x;
            smw[(4 * lane + 1) * 9 + p] = m4.y;
            smw[(4 * lane + 2) * 9 + p] = m4.z;
            smw[(4 * lane + 3) * 9 + p] = m4.w;
        }
        __syncwarp();
        float4 acc[8];
        #pragma unroll
        for (int p = 0; p < 8; p++) acc[p] = bs4;
        for (int c = 0; c < C_; c++) {
            float4 wr = *(float4*)&sWs[c * WS_STRIDE + 4 * lane];
            #pragma unroll
            for (int p = 0; p < 8; p++) {
                float mc = smw[c * 9 + p];
                acc[p].x = fmaf(wr.x, mc, acc[p].x);
                acc[p].y = fmaf(wr.y, mc, acc[p].y);
                acc[p].z = fmaf(wr.z, mc, acc[p].z);
                acc[p].w = fmaf(wr.w, mc, acc[p].w);
            }
        }
        #pragma unroll
        for (int p = 0; p < 8; p++) {
            size_t row = (size_t)g_pid[q0 + p];     // back to original order
            *(float4*)&out[row * C_ + 4 * lane] = acc[p];
        }
        __syncwarp();
    }
}

// ============================================================================
extern "C" void kernel_launch(void* const* d_in, const int* in_sizes, int n_in,
                              void* d_out, int out_size) {
    const float* feat = (const float*)d_in[0];
    const float* xyz  = (const float*)d_in[1];
    const float* Wr   = (const float*)d_in[2];
    const float* br   = (const float*)d_in[3];
    const float* Wv   = (const float*)d_in[4];
    const float* bv   = (const float*)d_in[5];
    const float* Ws   = (const float*)d_in[6];
    const float* bs   = (const float*)d_in[7];
    float* out = (float*)d_out;

    cudaFuncSetAttribute(prep_kernel, cudaFuncAttributeMaxDynamicSharedMemorySize, PREP_SMEM);
    cudaFuncSetAttribute(outproj_kernel, cudaFuncAttributeMaxDynamicSharedMemorySize, OUT_SMEM);

    void* ccnt;
    cudaGetSymbolAddress(&ccnt, g_cellcnt);
    cudaMemsetAsync(ccnt, 0, B_ * GC_ * sizeof(int));

    // grid build
    cellassign_kernel<<<BN_ / 256, 256>>>(xyz);
    scan_kernel<<<B_, 1024>>>();
    scatter_kernel<<<BN_ / 256, 256>>>(xyz);
    sortfix_kernel<<<B_ * GC_ / 128, 128>>>();

    // per-point EP/EQ/V (sorted order; 8-warp blocks for occupancy)
    prep_kernel<<<BN_ / 256, 256, PREP_SMEM>>>(feat, xyz, Wr, br, Wv, bv);

    // exact 36-NN, warp per query (tight wall radii + gated insert + bisection)
    knnq_kernel<<<BN_ / 8, 256>>>();

    // vector attention accumulate
    attn_kernel<<<BN_ / 8, 256>>>();

    // output projection (+ scatter back to original order)
    outproj_kernel<<<256, 256, OUT_SMEM>>>(Ws, bs, out);
}

// round 17
// speedup vs baseline: 1.4792x; 1.0690x over previous
#include <cuda_runtime.h>
#include <cuda_bf16.h>
#include <math_constants.h>

// Problem constants (fixed by setup_inputs)
#define B_   4
#define N_   8192
#define BN_  (B_ * N_)      // 32768 points
#define DIN  64
#define DPRE 67             // feature(64) + xyz(3)
#define C_   128            // D_OUT
#define K_   36

// spatial grid
#define G_   16
#define GC_  (G_ * G_ * G_)   // 4096 cells per batch

// ---------------- device scratch (no allocations allowed) ----------------
// NOTE: g_cellcnt starts zeroed (static init) and is re-zeroed at the END of
// each pipeline run (in outproj), so no memset launch is needed.
__device__ float  g_EP [BN_ * C_];   // exp(Wr_left @ pre)           (sorted order)
__device__ float  g_EQ [BN_ * C_];   // exp((Wr_r - Wr_l) @ pre + br)(sorted order)
__device__ float  g_V  [BN_ * C_];   // relu(Wv @ pre + bv)          (sorted order)
__device__ float  g_mid[BN_ * C_];   // attention output             (sorted order)
__device__ int    g_nbr[BN_ * K_];   // knn neighbor SORTED positions
__device__ int    g_cellcnt [B_ * GC_];
__device__ int    g_cellstart[B_ * GC_];
__device__ int    g_cellid[BN_];     // per original point: within-batch cell
__device__ int    g_rank  [BN_];     // atomic rank within cell (pre-sort)
__device__ float4 g_pts4 [BN_];      // sorted points (x,y,z,pad)
__device__ int    g_pid  [BN_];      // sorted pos -> original global id
__device__ int    g_spos [BN_];      // original global id -> sorted pos

// ---------------- fast exp (FMA pipe) ------------------------------------
__device__ __forceinline__ float fast_exp(float x) {
    float y = x * 1.4426950408889634f;      // x * log2(e)
    int   e = __float2int_rn(y);
    float f = y - (float)e;                 // f in [-0.5, 0.5]
    float p =            1.5403530393381609e-4f;
    p = fmaf(p, f, 1.3333558146428443e-3f);
    p = fmaf(p, f, 9.6181291076284770e-3f);
    p = fmaf(p, f, 5.5504108664821580e-2f);
    p = fmaf(p, f, 2.4022650695910070e-1f);
    p = fmaf(p, f, 6.9314718055994530e-1f);
    p = fmaf(p, f, 1.0f);
    float s = __int_as_float((e + 127) << 23);
    return p * s;
}

// ============================================================================
// Grid build
// ============================================================================
__global__ void cellassign_kernel(const float* __restrict__ xyz) {
    int m = blockIdx.x * blockDim.x + threadIdx.x;
    if (m >= BN_) return;
    int b = m >> 13;
    float x = xyz[(size_t)m * 3 + 0];
    float y = xyz[(size_t)m * 3 + 1];
    float z = xyz[(size_t)m * 3 + 2];
    int cx = min(G_ - 1, max(0, (int)(x * (float)G_)));
    int cy = min(G_ - 1, max(0, (int)(y * (float)G_)));
    int cz = min(G_ - 1, max(0, (int)(z * (float)G_)));
    int cell = (cx * G_ + cy) * G_ + cz;
    int r = atomicAdd(&g_cellcnt[b * GC_ + cell], 1);
    g_cellid[m] = cell;
    g_rank[m] = r;
}

__global__ void scan_kernel() {
    __shared__ int s[1024];
    int b = blockIdx.x;
    int t = threadIdx.x;
    int c0 = g_cellcnt[b * GC_ + 4 * t + 0];
    int c1 = g_cellcnt[b * GC_ + 4 * t + 1];
    int c2 = g_cellcnt[b * GC_ + 4 * t + 2];
    int c3 = g_cellcnt[b * GC_ + 4 * t + 3];
    int tot = c0 + c1 + c2 + c3;
    s[t] = tot;
    __syncthreads();
    for (int off = 1; off < 1024; off <<= 1) {
        int x = (t >= off) ? s[t - off] : 0;
        __syncthreads();
        s[t] += x;
        __syncthreads();
    }
    int excl = s[t] - tot;
    g_cellstart[b * GC_ + 4 * t + 0] = excl;
    g_cellstart[b * GC_ + 4 * t + 1] = excl + c0;
    g_cellstart[b * GC_ + 4 * t + 2] = excl + c0 + c1;
    g_cellstart[b * GC_ + 4 * t + 3] = excl + c0 + c1 + c2;
}

// scatter: pid only (pts4 is rebuilt by sortfix from xyz — one write, sorted order)
__global__ void scatter_kernel(const float* __restrict__ xyz) {
    int m = blockIdx.x * blockDim.x + threadIdx.x;
    if (m >= BN_) return;
    int b = m >> 13;
    int cell = g_cellid[m];
    int p = b * N_ + g_cellstart[b * GC_ + cell] + g_rank[m];
    g_pid[p] = m;
}

// sortfix: per-cell pid sort in a LOCAL array (L1-resident), single emit of
// g_pid/g_spos and g_pts4 (rebuilt from xyz — bit-identical values).
#define CELL_MAX 48
__global__ void sortfix_kernel(const float* __restrict__ xyz) {
    int i = blockIdx.x * blockDim.x + threadIdx.x;
    if (i >= B_ * GC_) return;
    int b = i / GC_;
    int cell = i - b * GC_;
    int start = b * N_ + g_cellstart[b * GC_ + cell];
    int cnt = g_cellcnt[b * GC_ + cell];

    if (cnt <= CELL_MAX) {
        int pl[CELL_MAX];
        for (int a = 0; a < cnt; a++) pl[a] = g_pid[start + a];
        for (int a = 1; a < cnt; a++) {
            int v = pl[a];
            int j = a - 1;
            while (j >= 0 && pl[j] > v) { pl[j + 1] = pl[j]; j--; }
            pl[j + 1] = v;
        }
        for (int a = 0; a < cnt; a++) {
            int pid = pl[a];
            g_pid[start + a] = pid;
            g_spos[pid] = start + a;
            const float* p = xyz + (size_t)pid * 3;
            g_pts4[start + a] = make_float4(p[0], p[1], p[2], 0.0f);
        }
    } else {
        // safety fallback (statistically never taken: Poisson(8) tail)
        for (int a = 1; a < cnt; a++) {
            int pid = g_pid[start + a];
            int j = a - 1;
            while (j >= 0 && g_pid[start + j] > pid) {
                g_pid[start + j + 1] = g_pid[start + j];
                j--;
            }
            g_pid[start + j + 1] = pid;
        }
        for (int a = 0; a < cnt; a++) {
            int pid = g_pid[start + a];
            g_spos[pid] = start + a;
            const float* p = xyz + (size_t)pid * 3;
            g_pts4[start + a] = make_float4(p[0], p[1], p[2], 0.0f);
        }
    }
}

// ============================================================================
// Kernel: per-point preprocessing (EP/EQ/V), written in SORTED order.
// 8-warp blocks sharing one smem weight copy (R16 config, proven).
// ============================================================================
#define PREP_WARPS 8
#define PREP_SMEM ((3 * DPRE * C_ + PREP_WARPS * 4 * 68) * 4)

__global__ void prep_kernel(const float* __restrict__ feat,
                            const float* __restrict__ xyz,
                            const float* __restrict__ Wr,
                            const float* __restrict__ br,
                            const float* __restrict__ Wv,
                            const float* __restrict__ bv) {
    extern __shared__ float sm[];
    float* sWA = sm;                       // Wr_left   [d][c]
    float* sWB = sm + DPRE * C_;           // Wr_right  [d][c] (then -= left)
    float* sWC = sm + 2 * DPRE * C_;       // Wv        [d][c]
    float* sPre = sm + 3 * DPRE * C_;      // [warp][4][68]

    int t = threadIdx.x;
    for (int i = t; i < C_ * 134; i += 256) {
        int c = i / 134, dd = i % 134;
        float v = Wr[i];
        if (dd < DPRE) sWA[dd * C_ + c] = v;
        else           sWB[(dd - DPRE) * C_ + c] = v;
    }
    for (int i = t; i < C_ * DPRE; i += 256) {
        int c = i / DPRE, d = i % DPRE;
        sWC[d * C_ + c] = Wv[i];
    }
    __syncthreads();
    for (int i = t; i < DPRE * C_; i += 256) sWB[i] -= sWA[i];
    __syncthreads();

    int w = t >> 5, lane = t & 31;
    float4 br4 = *(const float4*)&br[4 * lane];
    float4 bv4 = *(const float4*)&bv[4 * lane];
    float* spw = sPre + w * 4 * 68;

    int base = blockIdx.x * 256 + w * 32;   // 32 points per warp
    for (int it = 0; it < 8; it++) {
        int m0 = base + it * 4;
        #pragma unroll
        for (int p = 0; p < 4; p++) {
            int m = m0 + p;
            spw[p * 68 + lane]      = feat[(size_t)m * 64 + lane];
            spw[p * 68 + 32 + lane] = feat[(size_t)m * 64 + 32 + lane];
            if (lane < 3) spw[p * 68 + 64 + lane] = xyz[(size_t)m * 3 + lane];
        }
        __syncwarp();

        float aP[4][4], aQ[4][4], aV[4][4];
        #pragma unroll
        for (int p = 0; p < 4; p++)
            #pragma unroll
            for (int r = 0; r < 4; r++) { aP[p][r] = 0.f; aQ[p][r] = 0.f; aV[p][r] = 0.f; }

        for (int d = 0; d < DPRE; d++) {
            float4 wa = *(float4*)&sWA[d * C_ + 4 * lane];
            float4 wb = *(float4*)&sWB[d * C_ + 4 * lane];
            float4 wc = *(float4*)&sWC[d * C_ + 4 * lane];
            #pragma unroll
            for (int p = 0; p < 4; p++) {
                float x = spw[p * 68 + d];
                aP[p][0] = fmaf(wa.x, x, aP[p][0]);
                aP[p][1] = fmaf(wa.y, x, aP[p][1]);
                aP[p][2] = fmaf(wa.z, x, aP[p][2]);
                aP[p][3] = fmaf(wa.w, x, aP[p][3]);
                aQ[p][0] = fmaf(wb.x, x, aQ[p][0]);
                aQ[p][1] = fmaf(wb.y, x, aQ[p][1]);
                aQ[p][2] = fmaf(wb.z, x, aQ[p][2]);
                aQ[p][3] = fmaf(wb.w, x, aQ[p][3]);
                aV[p][0] = fmaf(wc.x, x, aV[p][0]);
                aV[p][1] = fmaf(wc.y, x, aV[p][1]);
                aV[p][2] = fmaf(wc.z, x, aV[p][2]);
                aV[p][3] = fmaf(wc.w, x, aV[p][3]);
            }
        }
        #pragma unroll
        for (int p = 0; p < 4; p++) {
            size_t sp = (size_t)g_spos[m0 + p];     // sorted destination
            float4 ep, eq, vv;
            ep.x = fast_exp(aP[p][0]); ep.y = fast_exp(aP[p][1]);
            ep.z = fast_exp(aP[p][2]); ep.w = fast_exp(aP[p][3]);
            eq.x = fast_exp(aQ[p][0] + br4.x); eq.y = fast_exp(aQ[p][1] + br4.y);
            eq.z = fast_exp(aQ[p][2] + br4.z); eq.w = fast_exp(aQ[p][3] + br4.w);
            vv.x = fmaxf(aV[p][0] + bv4.x, 0.f); vv.y = fmaxf(aV[p][1] + bv4.y, 0.f);
            vv.z = fmaxf(aV[p][2] + bv4.z, 0.f); vv.w = fmaxf(aV[p][3] + bv4.w, 0.f);
            *(float4*)&g_EP[sp * C_ + 4 * lane] = ep;
            *(float4*)&g_EQ[sp * C_ + 4 * lane] = eq;
            *(float4*)&g_V [sp * C_ + 4 * lane] = vv;
        }
        __syncwarp();
    }
}

// ============================================================================
// Kernel: exact 36-NN, WARP PER QUERY (R16 structure).
// CHANGE vs R16: bisection early-exits when count(<=mid) == 36 — that mid
// selects exactly the same 36-element set (compaction takes d<T then fills
// ties), so the output is identical while cutting ~2/3 of bisection rounds.
// ============================================================================
#define LLEN 10
#define INFBITS 0x7f800000u

__global__ void knnq_kernel() {
    int lane = threadIdx.x & 31;
    int W = blockIdx.x * (blockDim.x >> 5) + (threadIdx.x >> 5);
    int q = ((W & 7) << 12) | (W >> 3);       // balance shuffle (bijective)
    int b = q >> 13;

    float4 me = g_pts4[q];
    float qx = me.x, qy = me.y, qz = me.z;
    int cx = min(G_ - 1, max(0, (int)(qx * (float)G_)));
    int cy = min(G_ - 1, max(0, (int)(qy * (float)G_)));
    int cz = min(G_ - 1, max(0, (int)(qz * (float)G_)));

    const float h = 1.0f / (float)G_;
    const int cbase = b * GC_;
    const int pbase = b * N_;

    int clip = ((cx < 2 || cx > G_ - 3) ? 1 : 0)
             + ((cy < 2 || cy > G_ - 3) ? 1 : 0)
             + ((cz < 2 || cz > G_ - 3) ? 1 : 0);
    int r0 = (clip == 3) ? 4 : (clip ? 3 : 2);

    unsigned ld[LLEN];
    int      lp[LLEN];
    float    dth = 1e9f;

    int hwarp = lane >> 4;      // which column of the pair
    int lj    = lane & 15;      // index within half-warp

    for (int r = r0; ; r++) {
        #pragma unroll
        for (int s = 0; s < LLEN; s++) { ld[s] = INFBITS; lp[s] = -1; }

        int lox = max(cx - r, 0), hix = min(cx + r, G_ - 1);
        int loy = max(cy - r, 0), hiy = min(cy + r, G_ - 1);
        int loz = max(cz - r, 0), hiz = min(cz + r, G_ - 1);

        float d1 = (lox > 0)      ? (qx - (float)lox * h)        : 1e9f;
        float d2 = (hix < G_ - 1) ? ((float)(hix + 1) * h - qx)  : 1e9f;
        float d3 = (loy > 0)      ? (qy - (float)loy * h)        : 1e9f;
        float d4 = (hiy < G_ - 1) ? ((float)(hiy + 1) * h - qy)  : 1e9f;
        float d5 = (loz > 0)      ? (qz - (float)loz * h)        : 1e9f;
        float d6 = (hiz < G_ - 1) ? ((float)(hiz + 1) * h - qz)  : 1e9f;
        float dmin = fminf(fminf(fminf(d1, d2), fminf(d3, d4)), fminf(d5, d6));
        dth = fminf(dmin * dmin, 1e9f);

        int cnt_near = 0;

        for (int ix = lox; ix <= hix; ix++) {
            int colbase = cbase + (ix * G_) * G_;
            for (int iy0 = loy; iy0 <= hiy; iy0 += 2) {
                int iy = iy0 + hwarp;
                int s0 = 0, len = 0;
                if (iy <= hiy) {
                    int cc = colbase + iy * G_;
                    s0  = g_cellstart[cc + loz];
                    len = g_cellstart[cc + hiz] + g_cellcnt[cc + hiz] - s0;
                }
                int base = pbase + s0;
                int rot = (ix * 3 + iy0 * 5) & 15;   // de-skew lane<->j mapping
                for (int j = ((lj - rot) & 15); j < len; j += 16) {
                    float4 c = g_pts4[base + j];
                    float dx = c.x - qx, dy = c.y - qy, dz = c.z - qz;
                    float d = fmaf(dz, dz, fmaf(dy, dy, dx * dx));
                    if (d <= dth) {                        // relevance gate
                        cnt_near++;
                        unsigned db = __float_as_uint(d);
                        if (db < ld[LLEN - 1]) {
                            unsigned cd = db; int cp = base + j;
                            #pragma unroll
                            for (int s = 0; s < LLEN; s++) {
                                unsigned od = ld[s]; int op = lp[s];
                                if (cd < od) { ld[s] = cd; lp[s] = cp; cd = od; cp = op; }
                            }
                        }
                    }
                }
            }
        }

        unsigned tot = __reduce_add_sync(0xffffffffu, (unsigned)cnt_near);
        bool all = (lox == 0 && hix == G_ - 1 && loy == 0 && hiy == G_ - 1 &&
                    loz == 0 && hiz == G_ - 1);
        if (tot >= (unsigned)K_ || all) break;
    }

    // ---- merge: bisection for T with count(<=T) >= 36 (early-exit on ==36) --
    unsigned lo = __reduce_min_sync(0xffffffffu, ld[0]);
    unsigned hi = __float_as_uint(fminf(dth, 4.0f));   // certificate: count(<=dth)>=36
    if (hi < lo) hi = lo;
    int iter = 0;
    while (lo < hi && iter < 34) {
        unsigned mid = lo + ((hi - lo) >> 1);
        int c = 0;
        #pragma unroll
        for (int s = 0; s < LLEN; s++) c += (ld[s] <= mid) ? 1 : 0;
        unsigned tot = __reduce_add_sync(0xffffffffu, (unsigned)c);
        if (tot >= (unsigned)K_) {
            hi = mid;
            if (tot == (unsigned)K_) { lo = mid; break; }  // exact-set shortcut
        } else {
            lo = mid + 1;
        }
        iter++;
    }
    unsigned T = lo;

    // ---- compaction: all d < T, then fill to 36 with d == T (slot-major) ----
    unsigned lmlt = (1u << lane) - 1u;
    int base = 0;
    #pragma unroll
    for (int s = 0; s < LLEN; s++) {
        bool p = (ld[s] < T);
        unsigned m = __ballot_sync(0xffffffffu, p);
        if (p) g_nbr[(size_t)q * K_ + base + __popc(m & lmlt)] = lp[s];
        base += __popc(m);
    }
    #pragma unroll
    for (int s = 0; s < LLEN; s++) {
        if (base >= K_) break;                 // warp-uniform
        bool p = (ld[s] == T);
        unsigned m = __ballot_sync(0xffffffffu, p);
        int rk = __popc(m & lmlt);
        if (p && (base + rk) < K_) g_nbr[(size_t)q * K_ + base + rk] = lp[s];
        base += __popc(m);
    }
}

// ============================================================================
// Kernel: vector attention accumulate (warp/query, 256 threads).
// ============================================================================
__global__ void attn_kernel() {
    int gw   = (blockIdx.x * blockDim.x + threadIdx.x) >> 5;
    int lane = threadIdx.x & 31;
    if (gw >= BN_) return;
    size_t q = (size_t)gw;

    float4 eq = *(const float4*)&g_EQ[q * C_ + 4 * lane];
    int i0 = g_nbr[q * K_ + lane];
    int i1 = (lane < K_ - 32) ? g_nbr[q * K_ + 32 + lane] : 0;

    float4 acc = make_float4(0.f, 0.f, 0.f, 0.f);
    #pragma unroll 4
    for (int k = 0; k < K_; k++) {
        int j = (k < 32) ? __shfl_sync(0xffffffffu, i0, k)
                         : __shfl_sync(0xffffffffu, i1, k - 32);
        float4 ep = *(const float4*)&g_EP[(size_t)j * C_ + 4 * lane];
        float4 v  = *(const float4*)&g_V [(size_t)j * C_ + 4 * lane];
        float wx = ep.x * eq.x, wy = ep.y * eq.y, wz = ep.z * eq.z, ww = ep.w * eq.w;
        float part = (wx + wy) + (wz + ww);
        part += __shfl_xor_sync(0xffffffffu, part, 16);
        part += __shfl_xor_sync(0xffffffffu, part, 8);
        part += __shfl_xor_sync(0xffffffffu, part, 4);
        part += __shfl_xor_sync(0xffffffffu, part, 2);
        part += __shfl_xor_sync(0xffffffffu, part, 1);
        float rinv = __fdividef(1.0f, part);
        acc.x = fmaf(v.x, wx * rinv, acc.x);
        acc.y = fmaf(v.y, wy * rinv, acc.y);
        acc.z = fmaf(v.z, wz * rinv, acc.z);
        acc.w = fmaf(v.w, ww * rinv, acc.w);
    }
    *(float4*)&g_mid[q * C_ + 4 * lane] = acc;
}

// ============================================================================
// Kernel: output projection  out[pid[q]] = mid[q] @ Ws^T + bs.
// Also re-zeroes g_cellcnt for the NEXT pipeline run (after knnq, its last
// reader, has finished) — replaces the memset launch.
// ============================================================================
#define WS_STRIDE 132
#define OUT_SMEM  ((C_ * WS_STRIDE + 8 * C_ * 9) * 4)

__global__ void outproj_kernel(const float* __restrict__ Ws,
                               const float* __restrict__ bs,
                               float* __restrict__ out) {
    extern __shared__ float sm[];
    float* sWs  = sm;                    // [c][d] stride WS_STRIDE
    float* sMid = sm + C_ * WS_STRIDE;   // [warp][c][9]

    int t = threadIdx.x, w = t >> 5, lane = t & 31;

    // zero cell counts for the next run (graph replay / next launch)
    int gid = blockIdx.x * 256 + t;
    if (gid < B_ * GC_) g_cellcnt[gid] = 0;

    for (int i = t; i < C_ * C_; i += 256) {
        int d = i >> 7, c = i & 127;
        sWs[c * WS_STRIDE + d] = Ws[i];
    }
    __syncthreads();

    float4 bs4 = *(const float4*)&bs[4 * lane];
    float* smw = sMid + w * C_ * 9;
    int gw = blockIdx.x * 8 + w;                 // 2048 warps total

    for (int itq = 0; itq < 2; itq++) {
        int q0 = (gw + itq * 2048) * 8;
        #pragma unroll
        for (int p = 0; p < 8; p++) {
            float4 m4 = *(const float4*)&g_mid[(size_t)(q0 + p) * C_ + 4 * lane];
            smw[(4 * lane + 0) * 9 + p] = m4.x;
            smw[(4 * lane + 1) * 9 + p] = m4.y;
            smw[(4 * lane + 2) * 9 + p] = m4.z;
            smw[(4 * lane + 3) * 9 + p] = m4.w;
        }
        __syncwarp();
        float4 acc[8];
        #pragma unroll
        for (int p = 0; p < 8; p++) acc[p] = bs4;
        for (int c = 0; c < C_; c++) {
            float4 wr = *(float4*)&sWs[c * WS_STRIDE + 4 * lane];
            #pragma unroll
            for (int p = 0; p < 8; p++) {
                float mc = smw[c * 9 + p];
                acc[p].x = fmaf(wr.x, mc, acc[p].x);
                acc[p].y = fmaf(wr.y, mc, acc[p].y);
                acc[p].z = fmaf(wr.z, mc, acc[p].z);
                acc[p].w = fmaf(wr.w, mc, acc[p].w);
            }
        }
        #pragma unroll
        for (int p = 0; p < 8; p++) {
            size_t row = (size_t)g_pid[q0 + p];     // back to original order
            *(float4*)&out[row * C_ + 4 * lane] = acc[p];
        }
        __syncwarp();
    }
}

// ============================================================================
extern "C" void kernel_launch(void* const* d_in, const int* in_sizes, int n_in,
                              void* d_out, int out_size) {
    const float* feat = (const float*)d_in[0];
    const float* xyz  = (const float*)d_in[1];
    const float* Wr   = (const float*)d_in[2];
    const float* br   = (const float*)d_in[3];
    const float* Wv   = (const float*)d_in[4];
    const float* bv   = (const float*)d_in[5];
    const float* Ws   = (const float*)d_in[6];
    const float* bs   = (const float*)d_in[7];
    float* out = (float*)d_out;

    cudaFuncSetAttribute(prep_kernel, cudaFuncAttributeMaxDynamicSharedMemorySize, PREP_SMEM);
    cudaFuncSetAttribute(outproj_kernel, cudaFuncAttributeMaxDynamicSharedMemorySize, OUT_SMEM);

    // grid build (g_cellcnt is pre-zeroed: static init on first run, then
    // re-zeroed at the end of outproj on every run)
    cellassign_kernel<<<BN_ / 256, 256>>>(xyz);
    scan_kernel<<<B_, 1024>>>();
    scatter_kernel<<<BN_ / 256, 256>>>(xyz);
    sortfix_kernel<<<B_ * GC_ / 128, 128>>>(xyz);

    // per-point EP/EQ/V (sorted order; 8-warp blocks)
    prep_kernel<<<BN_ / 256, 256, PREP_SMEM>>>(feat, xyz, Wr, br, Wv, bv);

    // exact 36-NN, warp per query
    knnq_kernel<<<BN_ / 8, 256>>>();

    // vector attention accumulate
    attn_kernel<<<BN_ / 8, 256>>>();

    // output projection (+ scatter back + cellcnt re-zero)
    outproj_kernel<<<256, 256, OUT_SMEM>>>(Ws, bs, out);
}